// round 11
// baseline (speedup 1.0000x reference)
#include <cuda_runtime.h>
#include <cuda_bf16.h>
#include <cstdint>
#include <cstddef>
#include <cstring>

#define BS 256
#define KDIM 1024
#define NDIM 1024
#define NSTATES 20
#define TN 64
#define RCH 16
#define NTHREADS 256
#define MAXE 36
#define NCH 32                    // k32 chunks
#define XROWB 2064                // x smem row stride bytes (129*16 -> ldmatrix conflict-free)
#define WROWB 144                 // W smem row stride bytes (9*16)
#define XSPLITB (RCH * XROWB)     // 33024 per split
#define WBUFB (32 * WROWB)        // 4608 per split per buffer
#define WB_OFF (2 * XSPLITB)      // 66048
#define SMEMB (WB_OFF + 2 * 2 * WBUFB)   // 84480

__device__ int g_rows[MAXE][RCH];
__device__ int g_nrows[MAXE];
__device__ int g_state[MAXE];
__device__ int g_nentries;
__device__ __nv_bfloat16 g_xhi[BS * KDIM];
__device__ __nv_bfloat16 g_xlo[BS * KDIM];

__device__ __forceinline__ uint32_t s2u(const void* p) {
    uint32_t a;
    asm("{ .reg .u64 t; cvta.to.shared.u64 t, %1; cvt.u32.u64 %0, t; }" : "=r"(a) : "l"(p));
    return a;
}
__device__ __forceinline__ uint32_t bf2u(__nv_bfloat162 h) { uint32_t u; memcpy(&u, &h, 4); return u; }

// split (we, wo) -> bf16x2 hi pack {lo=we,hi=wo} and residual lo pack
__device__ __forceinline__ void wsplit(float we, float wo, uint32_t& h, uint32_t& l) {
    asm("cvt.rn.bf16x2.f32 %0, %1, %2;" : "=r"(h) : "f"(wo), "f"(we));
    const float fe = __uint_as_float(h << 16);
    const float fo = __uint_as_float(h & 0xffff0000u);
    asm("cvt.rn.bf16x2.f32 %0, %1, %2;" : "=r"(l) : "f"(wo - fo), "f"(we - fe));
}

#define LDM4(r0, r1, r2, r3, addr) \
    asm volatile("ldmatrix.sync.aligned.m8n8.x4.shared.b16 {%0,%1,%2,%3}, [%4];" \
                 : "=r"(r0), "=r"(r1), "=r"(r2), "=r"(r3) : "r"(addr))
#define LDM2T(r0, r1, addr) \
    asm volatile("ldmatrix.sync.aligned.m8n8.x2.trans.shared.b16 {%0,%1}, [%2];" \
                 : "=r"(r0), "=r"(r1) : "r"(addr))
#define MMA16816(d0, d1, d2, d3, a0, a1, a2, a3, b0, b1) \
    asm volatile("mma.sync.aligned.m16n8k16.row.col.f32.bf16.bf16.f32 " \
                 "{%0,%1,%2,%3}, {%4,%5,%6,%7}, {%8,%9}, {%0,%1,%2,%3};" \
                 : "+f"(d0), "+f"(d1), "+f"(d2), "+f"(d3) \
                 : "r"(a0), "r"(a1), "r"(a2), "r"(a3), "r"(b0), "r"(b1))

// ---- kernel A: compact work entries ----
__global__ void build_entries_kernel(const int* __restrict__ state)
{
    __shared__ int cnt[8][NSTATES];
    __shared__ int ebase[NSTATES];
    __shared__ int stot[NSTATES];
    const int t = threadIdx.x, w = t >> 5, lane = t & 31;
    if (t < 8 * NSTATES) ((int*)cnt)[t] = 0;
    __syncthreads();
    const int s = state[t];
    const unsigned grp = __match_any_sync(0xffffffffu, s);
    const int lr = __popc(grp & ((1u << lane) - 1u));
    if (lr == 0) cnt[w][s] = __popc(grp);
    __syncthreads();
    if (t < NSTATES) {
        int tot = 0;
#pragma unroll
        for (int ww = 0; ww < 8; ww++) tot += cnt[ww][t];
        stot[t] = tot;
    }
    __syncthreads();
    if (t == 0) {
        int b = 0;
        for (int i = 0; i < NSTATES; i++) { ebase[i] = b; b += (stot[i] + RCH - 1) / RCH; }
        g_nentries = b;
    }
    __syncthreads();
    int before = 0;
    for (int w2 = 0; w2 < w; w2++) before += cnt[w2][s];
    const int rank = before + lr;
    g_rows[ebase[s] + (rank >> 4)][rank & 15] = t;
    if (t < NSTATES) {
        const int nch = (stot[t] + RCH - 1) / RCH;
        for (int c = 0; c < nch; c++) {
            g_nrows[ebase[t] + c] = min(stot[t] - c * RCH, RCH);
            g_state[ebase[t] + c] = t;
        }
    }
}

// ---- kernel B: x -> bf16 hi/lo split ----
__global__ void xsplit_kernel(const float* __restrict__ x)
{
    const int i = blockIdx.x * 256 + threadIdx.x;   // float4 index
    const float4 v = ((const float4*)x)[i];
    const __nv_bfloat162 h01 = __floats2bfloat162_rn(v.x, v.y);
    const __nv_bfloat162 h23 = __floats2bfloat162_rn(v.z, v.w);
    const float r0 = v.x - __bfloat162float(__low2bfloat16(h01));
    const float r1 = v.y - __bfloat162float(__high2bfloat16(h01));
    const float r2 = v.z - __bfloat162float(__low2bfloat16(h23));
    const float r3 = v.w - __bfloat162float(__high2bfloat16(h23));
    ((uint2*)g_xhi)[i] = make_uint2(bf2u(h01), bf2u(h23));
    ((uint2*)g_xlo)[i] = make_uint2(bf2u(__floats2bfloat162_rn(r0, r1)),
                                    bf2u(__floats2bfloat162_rn(r2, r3)));
}

// ---- kernel C: HMMA masked GEMM per (n-tile, entry) ----
__global__ __launch_bounds__(NTHREADS, 2)
void masked_mma_kernel(const float* __restrict__ kern,
                       const float* __restrict__ masks,
                       float* __restrict__ out)
{
    extern __shared__ __align__(16) char sm[];
    __shared__ int rowlist[RCH];
    __shared__ int meta[2];

    const int e = blockIdx.y;
    if (e >= g_nentries) return;        // uniform exit before first sync

    const int t = threadIdx.x;
    const int wp = t >> 5, lane = t & 31;
    const int n0 = blockIdx.x * TN;
    if (t < RCH) rowlist[t] = g_rows[e][t];
    if (t == 16) meta[0] = g_nrows[e];
    if (t == 17) meta[1] = g_state[e];
    __syncthreads();
    const int nrows = meta[0], s = meta[1];

    // stage x hi/lo row-major (zero-padded rows), coalesced both sides
    for (int i = t; i < RCH * (KDIM / 8); i += NTHREADS) {   // uint4 tasks (8 bf16)
        const int r = i >> 7, kq = i & 127;
        uint4 vh = make_uint4(0, 0, 0, 0), vl = make_uint4(0, 0, 0, 0);
        if (r < nrows) {
            vh = *(const uint4*)(g_xhi + (size_t)rowlist[r] * KDIM + kq * 8);
            vl = *(const uint4*)(g_xlo + (size_t)rowlist[r] * KDIM + kq * 8);
        }
        *(uint4*)(sm + r * XROWB + kq * 16) = vh;
        *(uint4*)(sm + XSPLITB + r * XROWB + kq * 16) = vl;
    }
    __syncthreads();

    // W staging ids: thread handles rows {2*kpS, 2*kpS+1}, n quad nqS
    const int kpS = t >> 4;
    const int nqS = (t & 15) << 2;
    const float* mp = masks + (size_t)s * KDIM * NDIM + n0 + nqS;
    const float* kp_ = kern + n0 + nqS;

    float4 Mr0[2], Mr1[2], Kr0[2], Kr1[2];
#define LOADW(c, b) do { \
    const size_t o_ = (size_t)((c) * 32 + 2 * kpS) * NDIM; \
    Mr0[b] = *(const float4*)(mp + o_); \
    Mr1[b] = *(const float4*)(mp + o_ + NDIM); \
    Kr0[b] = *(const float4*)(kp_ + o_); \
    Kr1[b] = *(const float4*)(kp_ + o_ + NDIM); \
} while (0)
    LOADW(0, 0);
    LOADW(1, 1);

    // mma lane constants
    const int gid = lane >> 2, qd = lane & 3;
    const uint32_t xhiB = s2u(sm);
    const uint32_t xloB = xhiB + XSPLITB;
    const uint32_t xa_lane = (uint32_t)((lane & 15) * XROWB + (lane >> 4) * 16);
    const uint32_t wrow_lane = (uint32_t)((lane & 15) * WROWB);
    const uint32_t wcol = (uint32_t)(wp * 16);      // n0w * 2 bytes
    const uint32_t wB = xhiB + WB_OFF;

    float d0 = 0.f, d1 = 0.f, d2 = 0.f, d3 = 0.f;

    for (int c = 0; c < NCH; c++) {
        const int b = c & 1;
        // convert chunk c -> bf16 hi/lo W tiles (buffer b)
        {
            char* whiP = sm + WB_OFF + b * (2 * WBUFB);
            char* wloP = whiP + WBUFB;
            uint32_t h00, l00, h01, l01, h10, l10, h11, l11;
            wsplit(Mr0[b].x * Kr0[b].x, Mr0[b].y * Kr0[b].y, h00, l00);
            wsplit(Mr0[b].z * Kr0[b].z, Mr0[b].w * Kr0[b].w, h01, l01);
            wsplit(Mr1[b].x * Kr1[b].x, Mr1[b].y * Kr1[b].y, h10, l10);
            wsplit(Mr1[b].z * Kr1[b].z, Mr1[b].w * Kr1[b].w, h11, l11);
            const int r0off = (2 * kpS) * WROWB + nqS * 2;
            *(uint2*)(whiP + r0off) = make_uint2(h00, h01);
            *(uint2*)(whiP + r0off + WROWB) = make_uint2(h10, h11);
            *(uint2*)(wloP + r0off) = make_uint2(l00, l01);
            *(uint2*)(wloP + r0off + WROWB) = make_uint2(l10, l11);
        }
        __syncthreads();
        if (c + 2 < NCH) LOADW(c + 2, b);

        // consume buffer b: two k16 sub-chunks, 3 MMAs each (hh, hl, lh)
        const uint32_t whiB = wB + (uint32_t)b * (2 * WBUFB);
        const uint32_t wloB = whiB + WBUFB;
#pragma unroll
        for (int sb = 0; sb < 2; sb++) {
            const uint32_t kbyte = (uint32_t)(c * 32 + sb * 16) * 2;
            uint32_t ah0, ah1, ah2, ah3, al0, al1, al2, al3;
            LDM4(ah0, ah1, ah2, ah3, xhiB + xa_lane + kbyte);
            LDM4(al0, al1, al2, al3, xloB + xa_lane + kbyte);
            uint32_t bh0, bh1, bl0, bl1;
            const uint32_t wsub = (uint32_t)(sb * 16) * WROWB + wrow_lane + wcol;
            LDM2T(bh0, bh1, whiB + wsub);
            LDM2T(bl0, bl1, wloB + wsub);
            MMA16816(d0, d1, d2, d3, ah0, ah1, ah2, ah3, bh0, bh1);
            MMA16816(d0, d1, d2, d3, ah0, ah1, ah2, ah3, bl0, bl1);
            MMA16816(d0, d1, d2, d3, al0, al1, al2, al3, bh0, bh1);
        }
    }
#undef LOADW

    // epilogue: D frag -> relu -> out
    const int nn = n0 + (wp << 3) + (qd << 1);
    if (gid < nrows) {
        float2 v;
        v.x = fmaxf(d0, 0.f);
        v.y = fmaxf(d1, 0.f);
        *(float2*)&out[(size_t)rowlist[gid] * NDIM + nn] = v;
    }
    if (gid + 8 < nrows) {
        float2 v;
        v.x = fmaxf(d2, 0.f);
        v.y = fmaxf(d3, 0.f);
        *(float2*)&out[(size_t)rowlist[gid + 8] * NDIM + nn] = v;
    }
}

extern "C" void kernel_launch(void* const* d_in, const int* in_sizes, int n_in,
                              void* d_out, int out_size)
{
    const float* x = nullptr; const int* state = nullptr;
    const float* kern = nullptr; const float* masks = nullptr;
    for (int i = 0; i < n_in; i++) {
        switch (in_sizes[i]) {
            case BS * KDIM:             x = (const float*)d_in[i]; break;
            case BS:                    state = (const int*)d_in[i]; break;
            case KDIM * NDIM:           kern = (const float*)d_in[i]; break;
            case NSTATES * KDIM * NDIM: masks = (const float*)d_in[i]; break;
            default: break;
        }
    }
    float* out = (float*)d_out;

    cudaFuncSetAttribute(masked_mma_kernel,
                         cudaFuncAttributeMaxDynamicSharedMemorySize, SMEMB);

    build_entries_kernel<<<1, 256>>>(state);
    xsplit_kernel<<<BS * KDIM / 4 / 256, 256>>>(x);
    dim3 grid(NDIM / TN, MAXE);        // (16, 36)
    masked_mma_kernel<<<grid, NTHREADS, SMEMB>>>(kern, masks, out);
}

// round 12
// speedup vs baseline: 1.0192x; 1.0192x over previous
#include <cuda_runtime.h>
#include <cuda_bf16.h>
#include <cstdint>
#include <cstddef>
#include <cstring>

#define BS 256
#define KDIM 1024
#define NDIM 1024
#define NSTATES 20
#define TN 64
#define RCH 16
#define NTHREADS 256
#define MAXE 36
#define NCH 32                    // k32 chunks
#define XROWB 2064                // x smem row stride bytes (129*16 -> ldmatrix conflict-free)
#define WROWB 144                 // W smem row stride bytes (9*16)
#define XSPLITB (RCH * XROWB)     // 33024 per split
#define WBUFB (32 * WROWB)        // 4608 per split per buffer
#define WB_OFF (2 * XSPLITB)      // 66048
#define SMEMB (WB_OFF + 2 * 2 * WBUFB)   // 84480

__device__ int g_rows[MAXE][RCH];
__device__ int g_nrows[MAXE];
__device__ int g_state[MAXE];
__device__ int g_nentries;
__device__ __nv_bfloat16 g_xhi[BS * KDIM];
__device__ __nv_bfloat16 g_xlo[BS * KDIM];

__device__ __forceinline__ uint32_t s2u(const void* p) {
    uint32_t a;
    asm("{ .reg .u64 t; cvta.to.shared.u64 t, %1; cvt.u32.u64 %0, t; }" : "=r"(a) : "l"(p));
    return a;
}
__device__ __forceinline__ uint32_t bf2u(__nv_bfloat162 h) { uint32_t u; memcpy(&u, &h, 4); return u; }

// split (we, wo) -> bf16x2 hi pack {lo=we,hi=wo} and residual lo pack
__device__ __forceinline__ void wsplit(float we, float wo, uint32_t& h, uint32_t& l) {
    asm("cvt.rn.bf16x2.f32 %0, %1, %2;" : "=r"(h) : "f"(wo), "f"(we));
    const float fe = __uint_as_float(h << 16);
    const float fo = __uint_as_float(h & 0xffff0000u);
    asm("cvt.rn.bf16x2.f32 %0, %1, %2;" : "=r"(l) : "f"(wo - fo), "f"(we - fe));
}

#define LDM4(r0, r1, r2, r3, addr) \
    asm volatile("ldmatrix.sync.aligned.m8n8.x4.shared.b16 {%0,%1,%2,%3}, [%4];" \
                 : "=r"(r0), "=r"(r1), "=r"(r2), "=r"(r3) : "r"(addr))
#define LDM2T(r0, r1, addr) \
    asm volatile("ldmatrix.sync.aligned.m8n8.x2.trans.shared.b16 {%0,%1}, [%2];" \
                 : "=r"(r0), "=r"(r1) : "r"(addr))
#define MMA16816(d0, d1, d2, d3, a0, a1, a2, a3, b0, b1) \
    asm volatile("mma.sync.aligned.m16n8k16.row.col.f32.bf16.bf16.f32 " \
                 "{%0,%1,%2,%3}, {%4,%5,%6,%7}, {%8,%9}, {%0,%1,%2,%3};" \
                 : "+f"(d0), "+f"(d1), "+f"(d2), "+f"(d3) \
                 : "r"(a0), "r"(a1), "r"(a2), "r"(a3), "r"(b0), "r"(b1))

// ---- kernel A: compact work entries ----
__global__ void build_entries_kernel(const int* __restrict__ state)
{
    __shared__ int cnt[8][NSTATES];
    __shared__ int ebase[NSTATES];
    __shared__ int stot[NSTATES];
    const int t = threadIdx.x, w = t >> 5, lane = t & 31;
    if (t < 8 * NSTATES) ((int*)cnt)[t] = 0;
    __syncthreads();
    const int s = state[t];
    const unsigned grp = __match_any_sync(0xffffffffu, s);
    const int lr = __popc(grp & ((1u << lane) - 1u));
    if (lr == 0) cnt[w][s] = __popc(grp);
    __syncthreads();
    if (t < NSTATES) {
        int tot = 0;
#pragma unroll
        for (int ww = 0; ww < 8; ww++) tot += cnt[ww][t];
        stot[t] = tot;
    }
    __syncthreads();
    if (t == 0) {
        int b = 0;
        for (int i = 0; i < NSTATES; i++) { ebase[i] = b; b += (stot[i] + RCH - 1) / RCH; }
        g_nentries = b;
    }
    __syncthreads();
    int before = 0;
    for (int w2 = 0; w2 < w; w2++) before += cnt[w2][s];
    const int rank = before + lr;
    g_rows[ebase[s] + (rank >> 4)][rank & 15] = t;
    if (t < NSTATES) {
        const int nch = (stot[t] + RCH - 1) / RCH;
        for (int c = 0; c < nch; c++) {
            g_nrows[ebase[t] + c] = min(stot[t] - c * RCH, RCH);
            g_state[ebase[t] + c] = t;
        }
    }
}

// ---- kernel B: x -> bf16 hi/lo split ----
__global__ void xsplit_kernel(const float* __restrict__ x)
{
    const int i = blockIdx.x * 256 + threadIdx.x;   // float4 index
    const float4 v = ((const float4*)x)[i];
    const __nv_bfloat162 h01 = __floats2bfloat162_rn(v.x, v.y);
    const __nv_bfloat162 h23 = __floats2bfloat162_rn(v.z, v.w);
    const float r0 = v.x - __bfloat162float(__low2bfloat16(h01));
    const float r1 = v.y - __bfloat162float(__high2bfloat16(h01));
    const float r2 = v.z - __bfloat162float(__low2bfloat16(h23));
    const float r3 = v.w - __bfloat162float(__high2bfloat16(h23));
    ((uint2*)g_xhi)[i] = make_uint2(bf2u(h01), bf2u(h23));
    ((uint2*)g_xlo)[i] = make_uint2(bf2u(__floats2bfloat162_rn(r0, r1)),
                                    bf2u(__floats2bfloat162_rn(r2, r3)));
}

// ---- kernel C: HMMA masked GEMM per (n-tile, entry) ----
__global__ __launch_bounds__(NTHREADS, 2)
void masked_mma_kernel(const float* __restrict__ kern,
                       const float* __restrict__ masks,
                       float* __restrict__ out)
{
    extern __shared__ __align__(16) char sm[];
    __shared__ int rowlist[RCH];
    __shared__ int meta[2];

    const int e = blockIdx.y;
    if (e >= g_nentries) return;        // uniform exit before first sync

    const int t = threadIdx.x;
    const int wp = t >> 5, lane = t & 31;
    const int n0 = blockIdx.x * TN;
    if (t < RCH) rowlist[t] = g_rows[e][t];
    if (t == 16) meta[0] = g_nrows[e];
    if (t == 17) meta[1] = g_state[e];
    __syncthreads();
    const int nrows = meta[0], s = meta[1];

    // stage x hi/lo row-major (zero-padded rows), coalesced both sides
    for (int i = t; i < RCH * (KDIM / 8); i += NTHREADS) {   // uint4 tasks (8 bf16)
        const int r = i >> 7, kq = i & 127;
        uint4 vh = make_uint4(0, 0, 0, 0), vl = make_uint4(0, 0, 0, 0);
        if (r < nrows) {
            vh = *(const uint4*)(g_xhi + (size_t)rowlist[r] * KDIM + kq * 8);
            vl = *(const uint4*)(g_xlo + (size_t)rowlist[r] * KDIM + kq * 8);
        }
        *(uint4*)(sm + r * XROWB + kq * 16) = vh;
        *(uint4*)(sm + XSPLITB + r * XROWB + kq * 16) = vl;
    }
    __syncthreads();

    // W staging ids: thread handles rows {2*kpS, 2*kpS+1}, n quad nqS
    const int kpS = t >> 4;
    const int nqS = (t & 15) << 2;
    const float* mp = masks + (size_t)s * KDIM * NDIM + n0 + nqS;
    const float* kp_ = kern + n0 + nqS;

    float4 Mr0[2], Mr1[2], Kr0[2], Kr1[2];
#define LOADW(c, b) do { \
    const size_t o_ = (size_t)((c) * 32 + 2 * kpS) * NDIM; \
    Mr0[b] = *(const float4*)(mp + o_); \
    Mr1[b] = *(const float4*)(mp + o_ + NDIM); \
    Kr0[b] = *(const float4*)(kp_ + o_); \
    Kr1[b] = *(const float4*)(kp_ + o_ + NDIM); \
} while (0)
    LOADW(0, 0);
    LOADW(1, 1);

    // mma lane constants
    const int gid = lane >> 2, qd = lane & 3;
    const uint32_t xhiB = s2u(sm);
    const uint32_t xloB = xhiB + XSPLITB;
    const uint32_t xa_lane = (uint32_t)((lane & 15) * XROWB + (lane >> 4) * 16);
    const uint32_t wrow_lane = (uint32_t)((lane & 15) * WROWB);
    const uint32_t wcol = (uint32_t)(wp * 16);      // n0w * 2 bytes
    const uint32_t wB = xhiB + WB_OFF;

    float d0 = 0.f, d1 = 0.f, d2 = 0.f, d3 = 0.f;

    for (int c = 0; c < NCH; c++) {
        const int b = c & 1;
        // convert chunk c -> bf16 hi/lo W tiles (buffer b)
        {
            char* whiP = sm + WB_OFF + b * (2 * WBUFB);
            char* wloP = whiP + WBUFB;
            uint32_t h00, l00, h01, l01, h10, l10, h11, l11;
            wsplit(Mr0[b].x * Kr0[b].x, Mr0[b].y * Kr0[b].y, h00, l00);
            wsplit(Mr0[b].z * Kr0[b].z, Mr0[b].w * Kr0[b].w, h01, l01);
            wsplit(Mr1[b].x * Kr1[b].x, Mr1[b].y * Kr1[b].y, h10, l10);
            wsplit(Mr1[b].z * Kr1[b].z, Mr1[b].w * Kr1[b].w, h11, l11);
            const int r0off = (2 * kpS) * WROWB + nqS * 2;
            *(uint2*)(whiP + r0off) = make_uint2(h00, h01);
            *(uint2*)(whiP + r0off + WROWB) = make_uint2(h10, h11);
            *(uint2*)(wloP + r0off) = make_uint2(l00, l01);
            *(uint2*)(wloP + r0off + WROWB) = make_uint2(l10, l11);
        }
        __syncthreads();
        if (c + 2 < NCH) LOADW(c + 2, b);

        // consume buffer b: two k16 sub-chunks, 3 MMAs each (hh, hl, lh)
        const uint32_t whiB = wB + (uint32_t)b * (2 * WBUFB);
        const uint32_t wloB = whiB + WBUFB;
#pragma unroll
        for (int sb = 0; sb < 2; sb++) {
            const uint32_t kbyte = (uint32_t)(c * 32 + sb * 16) * 2;
            uint32_t ah0, ah1, ah2, ah3, al0, al1, al2, al3;
            LDM4(ah0, ah1, ah2, ah3, xhiB + xa_lane + kbyte);
            LDM4(al0, al1, al2, al3, xloB + xa_lane + kbyte);
            uint32_t bh0, bh1, bl0, bl1;
            const uint32_t wsub = (uint32_t)(sb * 16) * WROWB + wrow_lane + wcol;
            LDM2T(bh0, bh1, whiB + wsub);
            LDM2T(bl0, bl1, wloB + wsub);
            MMA16816(d0, d1, d2, d3, ah0, ah1, ah2, ah3, bh0, bh1);
            MMA16816(d0, d1, d2, d3, ah0, ah1, ah2, ah3, bl0, bl1);
            MMA16816(d0, d1, d2, d3, al0, al1, al2, al3, bh0, bh1);
        }
    }
#undef LOADW

    // epilogue: D frag -> relu -> out
    const int nn = n0 + (wp << 3) + (qd << 1);
    if (gid < nrows) {
        float2 v;
        v.x = fmaxf(d0, 0.f);
        v.y = fmaxf(d1, 0.f);
        *(float2*)&out[(size_t)rowlist[gid] * NDIM + nn] = v;
    }
    if (gid + 8 < nrows) {
        float2 v;
        v.x = fmaxf(d2, 0.f);
        v.y = fmaxf(d3, 0.f);
        *(float2*)&out[(size_t)rowlist[gid + 8] * NDIM + nn] = v;
    }
}

extern "C" void kernel_launch(void* const* d_in, const int* in_sizes, int n_in,
                              void* d_out, int out_size)
{
    const float* x = nullptr; const int* state = nullptr;
    const float* kern = nullptr; const float* masks = nullptr;
    for (int i = 0; i < n_in; i++) {
        switch (in_sizes[i]) {
            case BS * KDIM:             x = (const float*)d_in[i]; break;
            case BS:                    state = (const int*)d_in[i]; break;
            case KDIM * NDIM:           kern = (const float*)d_in[i]; break;
            case NSTATES * KDIM * NDIM: masks = (const float*)d_in[i]; break;
            default: break;
        }
    }
    float* out = (float*)d_out;

    cudaFuncSetAttribute(masked_mma_kernel,
                         cudaFuncAttributeMaxDynamicSharedMemorySize, SMEMB);

    build_entries_kernel<<<1, 256>>>(state);
    xsplit_kernel<<<BS * KDIM / 4 / 256, 256>>>(x);
    dim3 grid(NDIM / TN, MAXE);        // (16, 36)
    masked_mma_kernel<<<grid, NTHREADS, SMEMB>>>(kern, masks, out);
}

// round 13
// speedup vs baseline: 1.0332x; 1.0137x over previous
#include <cuda_runtime.h>
#include <cuda_bf16.h>
#include <cstdint>
#include <cstddef>
#include <cstring>

#define BS 256
#define KDIM 1024
#define NDIM 1024
#define NSTATES 20
#define TN 64
#define RCH 16
#define NTHREADS 256
#define MAXE 36
#define NCH 32                    // k32 chunks
#define XROWB 2064                // x smem row stride bytes (129*16 -> ldmatrix conflict-free)
#define WROWB 144                 // W smem row stride bytes (9*16)
#define XSPLITB (RCH * XROWB)     // 33024 per split
#define WBUFB (32 * WROWB)        // 4608 per split per buffer
#define WB_OFF (2 * XSPLITB)      // 66048
#define SMEMB (WB_OFF + 2 * 2 * WBUFB)   // 84480

__device__ int g_rows[MAXE][RCH];
__device__ int g_nrows[MAXE];
__device__ int g_state[MAXE];
__device__ int g_nentries;
__device__ __nv_bfloat16 g_xhi[BS * KDIM];
__device__ __nv_bfloat16 g_xlo[BS * KDIM];

__device__ __forceinline__ uint32_t s2u(const void* p) {
    uint32_t a;
    asm("{ .reg .u64 t; cvta.to.shared.u64 t, %1; cvt.u32.u64 %0, t; }" : "=r"(a) : "l"(p));
    return a;
}
__device__ __forceinline__ uint32_t bf2u(__nv_bfloat162 h) { uint32_t u; memcpy(&u, &h, 4); return u; }

// split (we, wo) -> bf16x2 hi pack {lo=we,hi=wo} and residual lo pack
__device__ __forceinline__ void wsplit(float we, float wo, uint32_t& h, uint32_t& l) {
    asm("cvt.rn.bf16x2.f32 %0, %1, %2;" : "=r"(h) : "f"(wo), "f"(we));
    const float fe = __uint_as_float(h << 16);
    const float fo = __uint_as_float(h & 0xffff0000u);
    asm("cvt.rn.bf16x2.f32 %0, %1, %2;" : "=r"(l) : "f"(wo - fo), "f"(we - fe));
}

#define LDM4(r0, r1, r2, r3, addr) \
    asm volatile("ldmatrix.sync.aligned.m8n8.x4.shared.b16 {%0,%1,%2,%3}, [%4];" \
                 : "=r"(r0), "=r"(r1), "=r"(r2), "=r"(r3) : "r"(addr))
#define LDM2T(r0, r1, addr) \
    asm volatile("ldmatrix.sync.aligned.m8n8.x2.trans.shared.b16 {%0,%1}, [%2];" \
                 : "=r"(r0), "=r"(r1) : "r"(addr))
#define MMA16816(d0, d1, d2, d3, a0, a1, a2, a3, b0, b1) \
    asm volatile("mma.sync.aligned.m16n8k16.row.col.f32.bf16.bf16.f32 " \
                 "{%0,%1,%2,%3}, {%4,%5,%6,%7}, {%8,%9}, {%0,%1,%2,%3};" \
                 : "+f"(d0), "+f"(d1), "+f"(d2), "+f"(d3) \
                 : "r"(a0), "r"(a1), "r"(a2), "r"(a3), "r"(b0), "r"(b1))

// ---- kernel A: compact work entries ----
__global__ void build_entries_kernel(const int* __restrict__ state)
{
    __shared__ int cnt[8][NSTATES];
    __shared__ int ebase[NSTATES];
    __shared__ int stot[NSTATES];
    const int t = threadIdx.x, w = t >> 5, lane = t & 31;
    if (t < 8 * NSTATES) ((int*)cnt)[t] = 0;
    __syncthreads();
    const int s = state[t];
    const unsigned grp = __match_any_sync(0xffffffffu, s);
    const int lr = __popc(grp & ((1u << lane) - 1u));
    if (lr == 0) cnt[w][s] = __popc(grp);
    __syncthreads();
    if (t < NSTATES) {
        int tot = 0;
#pragma unroll
        for (int ww = 0; ww < 8; ww++) tot += cnt[ww][t];
        stot[t] = tot;
    }
    __syncthreads();
    if (t == 0) {
        int b = 0;
        for (int i = 0; i < NSTATES; i++) { ebase[i] = b; b += (stot[i] + RCH - 1) / RCH; }
        g_nentries = b;
    }
    __syncthreads();
    int before = 0;
    for (int w2 = 0; w2 < w; w2++) before += cnt[w2][s];
    const int rank = before + lr;
    g_rows[ebase[s] + (rank >> 4)][rank & 15] = t;
    if (t < NSTATES) {
        const int nch = (stot[t] + RCH - 1) / RCH;
        for (int c = 0; c < nch; c++) {
            g_nrows[ebase[t] + c] = min(stot[t] - c * RCH, RCH);
            g_state[ebase[t] + c] = t;
        }
    }
}

// ---- kernel B: x -> bf16 hi/lo split ----
__global__ void xsplit_kernel(const float* __restrict__ x)
{
    const int i = blockIdx.x * 256 + threadIdx.x;   // float4 index
    const float4 v = ((const float4*)x)[i];
    const __nv_bfloat162 h01 = __floats2bfloat162_rn(v.x, v.y);
    const __nv_bfloat162 h23 = __floats2bfloat162_rn(v.z, v.w);
    const float r0 = v.x - __bfloat162float(__low2bfloat16(h01));
    const float r1 = v.y - __bfloat162float(__high2bfloat16(h01));
    const float r2 = v.z - __bfloat162float(__low2bfloat16(h23));
    const float r3 = v.w - __bfloat162float(__high2bfloat16(h23));
    ((uint2*)g_xhi)[i] = make_uint2(bf2u(h01), bf2u(h23));
    ((uint2*)g_xlo)[i] = make_uint2(bf2u(__floats2bfloat162_rn(r0, r1)),
                                    bf2u(__floats2bfloat162_rn(r2, r3)));
}

// ---- kernel C: HMMA masked GEMM per (n-tile, entry) ----
__global__ __launch_bounds__(NTHREADS, 2)
void masked_mma_kernel(const float* __restrict__ kern,
                       const float* __restrict__ masks,
                       float* __restrict__ out)
{
    extern __shared__ __align__(16) char sm[];
    __shared__ int rowlist[RCH];
    __shared__ int meta[2];

    const int e = blockIdx.y;
    if (e >= g_nentries) return;        // uniform exit before first sync

    const int t = threadIdx.x;
    const int wp = t >> 5, lane = t & 31;
    const int n0 = blockIdx.x * TN;
    if (t < RCH) rowlist[t] = g_rows[e][t];
    if (t == 16) meta[0] = g_nrows[e];
    if (t == 17) meta[1] = g_state[e];
    __syncthreads();
    const int nrows = meta[0], s = meta[1];

    // stage x hi/lo row-major (zero-padded rows), coalesced both sides
    for (int i = t; i < RCH * (KDIM / 8); i += NTHREADS) {   // uint4 tasks (8 bf16)
        const int r = i >> 7, kq = i & 127;
        uint4 vh = make_uint4(0, 0, 0, 0), vl = make_uint4(0, 0, 0, 0);
        if (r < nrows) {
            vh = *(const uint4*)(g_xhi + (size_t)rowlist[r] * KDIM + kq * 8);
            vl = *(const uint4*)(g_xlo + (size_t)rowlist[r] * KDIM + kq * 8);
        }
        *(uint4*)(sm + r * XROWB + kq * 16) = vh;
        *(uint4*)(sm + XSPLITB + r * XROWB + kq * 16) = vl;
    }
    __syncthreads();

    // W staging ids: thread handles rows {2*kpS, 2*kpS+1}, n quad nqS
    const int kpS = t >> 4;
    const int nqS = (t & 15) << 2;
    const float* mp = masks + (size_t)s * KDIM * NDIM + n0 + nqS;
    const float* kp_ = kern + n0 + nqS;

    float4 Mr0[2], Mr1[2], Kr0[2], Kr1[2];
#define LOADW(c, b) do { \
    const size_t o_ = (size_t)((c) * 32 + 2 * kpS) * NDIM; \
    Mr0[b] = *(const float4*)(mp + o_); \
    Mr1[b] = *(const float4*)(mp + o_ + NDIM); \
    Kr0[b] = *(const float4*)(kp_ + o_); \
    Kr1[b] = *(const float4*)(kp_ + o_ + NDIM); \
} while (0)
    LOADW(0, 0);
    LOADW(1, 1);

    // mma lane constants
    const int gid = lane >> 2, qd = lane & 3;
    const uint32_t xhiB = s2u(sm);
    const uint32_t xloB = xhiB + XSPLITB;
    const uint32_t xa_lane = (uint32_t)((lane & 15) * XROWB + (lane >> 4) * 16);
    const uint32_t wrow_lane = (uint32_t)((lane & 15) * WROWB);
    const uint32_t wcol = (uint32_t)(wp * 16);      // n0w * 2 bytes
    const uint32_t wB = xhiB + WB_OFF;

    float d0 = 0.f, d1 = 0.f, d2 = 0.f, d3 = 0.f;

    for (int c = 0; c < NCH; c++) {
        const int b = c & 1;
        // convert chunk c -> bf16 hi/lo W tiles (buffer b)
        {
            char* whiP = sm + WB_OFF + b * (2 * WBUFB);
            char* wloP = whiP + WBUFB;
            uint32_t h00, l00, h01, l01, h10, l10, h11, l11;
            wsplit(Mr0[b].x * Kr0[b].x, Mr0[b].y * Kr0[b].y, h00, l00);
            wsplit(Mr0[b].z * Kr0[b].z, Mr0[b].w * Kr0[b].w, h01, l01);
            wsplit(Mr1[b].x * Kr1[b].x, Mr1[b].y * Kr1[b].y, h10, l10);
            wsplit(Mr1[b].z * Kr1[b].z, Mr1[b].w * Kr1[b].w, h11, l11);
            const int r0off = (2 * kpS) * WROWB + nqS * 2;
            *(uint2*)(whiP + r0off) = make_uint2(h00, h01);
            *(uint2*)(whiP + r0off + WROWB) = make_uint2(h10, h11);
            *(uint2*)(wloP + r0off) = make_uint2(l00, l01);
            *(uint2*)(wloP + r0off + WROWB) = make_uint2(l10, l11);
        }
        __syncthreads();
        if (c + 2 < NCH) LOADW(c + 2, b);

        // consume buffer b: two k16 sub-chunks, 3 MMAs each (hh, hl, lh)
        const uint32_t whiB = wB + (uint32_t)b * (2 * WBUFB);
        const uint32_t wloB = whiB + WBUFB;
#pragma unroll
        for (int sb = 0; sb < 2; sb++) {
            const uint32_t kbyte = (uint32_t)(c * 32 + sb * 16) * 2;
            uint32_t ah0, ah1, ah2, ah3, al0, al1, al2, al3;
            LDM4(ah0, ah1, ah2, ah3, xhiB + xa_lane + kbyte);
            LDM4(al0, al1, al2, al3, xloB + xa_lane + kbyte);
            uint32_t bh0, bh1, bl0, bl1;
            const uint32_t wsub = (uint32_t)(sb * 16) * WROWB + wrow_lane + wcol;
            LDM2T(bh0, bh1, whiB + wsub);
            LDM2T(bl0, bl1, wloB + wsub);
            MMA16816(d0, d1, d2, d3, ah0, ah1, ah2, ah3, bh0, bh1);
            MMA16816(d0, d1, d2, d3, ah0, ah1, ah2, ah3, bl0, bl1);
            MMA16816(d0, d1, d2, d3, al0, al1, al2, al3, bh0, bh1);
        }
    }
#undef LOADW

    // epilogue: D frag -> relu -> out
    const int nn = n0 + (wp << 3) + (qd << 1);
    if (gid < nrows) {
        float2 v;
        v.x = fmaxf(d0, 0.f);
        v.y = fmaxf(d1, 0.f);
        *(float2*)&out[(size_t)rowlist[gid] * NDIM + nn] = v;
    }
    if (gid + 8 < nrows) {
        float2 v;
        v.x = fmaxf(d2, 0.f);
        v.y = fmaxf(d3, 0.f);
        *(float2*)&out[(size_t)rowlist[gid + 8] * NDIM + nn] = v;
    }
}

extern "C" void kernel_launch(void* const* d_in, const int* in_sizes, int n_in,
                              void* d_out, int out_size)
{
    const float* x = nullptr; const int* state = nullptr;
    const float* kern = nullptr; const float* masks = nullptr;
    for (int i = 0; i < n_in; i++) {
        switch (in_sizes[i]) {
            case BS * KDIM:             x = (const float*)d_in[i]; break;
            case BS:                    state = (const int*)d_in[i]; break;
            case KDIM * NDIM:           kern = (const float*)d_in[i]; break;
            case NSTATES * KDIM * NDIM: masks = (const float*)d_in[i]; break;
            default: break;
        }
    }
    float* out = (float*)d_out;

    cudaFuncSetAttribute(masked_mma_kernel,
                         cudaFuncAttributeMaxDynamicSharedMemorySize, SMEMB);

    build_entries_kernel<<<1, 256>>>(state);
    xsplit_kernel<<<BS * KDIM / 4 / 256, 256>>>(x);
    dim3 grid(NDIM / TN, MAXE);        // (16, 36)
    masked_mma_kernel<<<grid, NTHREADS, SMEMB>>>(kern, masks, out);
}